// round 15
// baseline (speedup 1.0000x reference)
#include <cuda_runtime.h>

#define NNODES 100000
#define NEDGES 1600000
#define NREL 4

// Scratch (static __device__ arrays — allocation-free per harness rules)
__device__ __align__(16) float g_S1[NREL * NNODES * 16];  // 25.6 MB
__device__ __align__(16) float g_S2[NREL * NNODES * 16];  // 25.6 MB
__device__ __align__(16) float g_S3[NREL * NNODES * 32];  // 51.2 MB
__device__ int   g_cnt[NREL * NNODES];                    // 1.6 MB
__device__ __align__(16) float g_h1[NNODES * 16];
__device__ __align__(16) float g_h2[NNODES * 32];

typedef unsigned long long ull;

// ---------------------------------------------------------------------------
// f32x2 packed-FMA helpers (sm_100+)
// ---------------------------------------------------------------------------
__device__ __forceinline__ void ffma2(ull& acc, ull a, ull b) {
    asm("fma.rn.f32x2 %0, %1, %2, %0;" : "+l"(acc) : "l"(a), "l"(b));
}
__device__ __forceinline__ ull bcast2(float v) {
    ull r;
    unsigned int u = __float_as_uint(v);
    asm("mov.b64 %0, {%1, %1};" : "=l"(r) : "r"(u));
    return r;
}

// Multiply-accumulate one weight row (COLS floats, broadcast from smem) by a
// scalar input value into packed accumulators.
template <int COLS>
__device__ __forceinline__ void mac_row(ull* acc,
                                        const float* __restrict__ wrow,
                                        float v) {
    const ull v2 = bcast2(v);
#pragma unroll
    for (int j = 0; j < COLS / 4; j++) {
        ulonglong2 w = *reinterpret_cast<const ulonglong2*>(wrow + 4 * j);
        ffma2(acc[2 * j], v2, w.x);
        ffma2(acc[2 * j + 1], v2, w.y);
    }
}

// ---------------------------------------------------------------------------
// Scatter: S[r, dst, :] += h[src, :] via vectorized L2 reductions.
// (Champion, unchanged.)
// ---------------------------------------------------------------------------
template <int DIN, bool COUNT>
__global__ void scatter_kernel(const float* __restrict__ h,
                               const int* __restrict__ src,
                               const int* __restrict__ dst,
                               const int* __restrict__ et,
                               float* __restrict__ S,
                               int* __restrict__ cnt, int n, int e) {
    constexpr int CH = DIN / 4;
    int t = blockIdx.x * blockDim.x + threadIdx.x;
    int ed = t / CH;
    int c  = t - ed * CH;
    if (ed >= e) return;
    int s = __ldg(src + ed);
    int d = __ldg(dst + ed);
    int r = __ldg(et + ed);
    const float4 v = *reinterpret_cast<const float4*>(h + (size_t)s * DIN + c * 4);
    float* p = S + ((size_t)r * n + d) * DIN + c * 4;
    asm volatile("red.global.add.v4.f32 [%0], {%1,%2,%3,%4};"
                 :: "l"(p), "f"(v.x), "f"(v.y), "f"(v.z), "f"(v.w)
                 : "memory");
    if (COUNT && c == 0) atomicAdd(cnt + r * n + d, 1);
}

// ---------------------------------------------------------------------------
// Champion combine (fat thread; layer 1 only):
//   out[i] = bias + x[i]@root + sum_r (S[r,i]/max(cnt,1)) @ W_r
// ---------------------------------------------------------------------------
template <int DIN, int DOUT, bool RELU>
__global__ void __launch_bounds__(128)
combine_kernel(const float* __restrict__ xin,
               const float* __restrict__ S,
               const int* __restrict__ cnt,
               const float* __restrict__ W,     // [R, DIN, DOUT]
               const float* __restrict__ root,  // [DIN, DOUT]
               const float* __restrict__ bias,  // [DOUT]
               float* __restrict__ out, int n) {
    __shared__ __align__(16) float sw[5 * DIN * DOUT];
    const int tid = threadIdx.x;
    for (int i = tid; i < DIN * DOUT; i += 128) sw[i] = root[i];
    for (int i = tid; i < NREL * DIN * DOUT; i += 128) sw[DIN * DOUT + i] = W[i];
    __syncthreads();

    const int node = blockIdx.x * 128 + tid;
    if (node >= n) return;

    ull acc[DOUT / 2];
#pragma unroll
    for (int j = 0; j < DOUT / 2; j++)
        acc[j] = reinterpret_cast<const ull*>(bias)[j];

    float inv[NREL];
#pragma unroll
    for (int r = 0; r < NREL; r++) {
        int c = __ldg(cnt + r * n + node);
        inv[r] = 1.0f / (float)(c > 1 ? c : 1);
    }

#pragma unroll
    for (int rb = 0; rb < 5; rb++) {
        const float scale = (rb == 0) ? 1.0f : inv[rb - 1];
        const float4* __restrict__ base = reinterpret_cast<const float4*>(
            (rb == 0) ? xin + (size_t)node * DIN
                      : S + ((size_t)(rb - 1) * n + node) * DIN);
        const float* __restrict__ wr = sw + rb * DIN * DOUT;
        for (int c4 = 0; c4 < DIN / 4; c4++) {
            float4 v4 = __ldg(base + c4);
            mac_row<DOUT>(acc, wr + (c4 * 4 + 0) * DOUT, v4.x * scale);
            mac_row<DOUT>(acc, wr + (c4 * 4 + 1) * DOUT, v4.y * scale);
            mac_row<DOUT>(acc, wr + (c4 * 4 + 2) * DOUT, v4.z * scale);
            mac_row<DOUT>(acc, wr + (c4 * 4 + 3) * DOUT, v4.w * scale);
        }
    }

    float* op = out + (size_t)node * DOUT;
#pragma unroll
    for (int j = 0; j < DOUT / 2; j++) {
        float2 f = *reinterpret_cast<float2*>(&acc[j]);
        if (RELU) {
            f.x = fmaxf(f.x, 0.0f);
            f.y = fmaxf(f.y, 0.0f);
        }
        reinterpret_cast<float2*>(op)[j] = f;
    }
}

// ---------------------------------------------------------------------------
// Persistent combine (R7 structure, generalized over COLS):
// fixed grid, weights staged once per block, NT=2 nodes/thread, weight
// registers reused across both nodes (LDS:FFMA2 = 1:4), 1-block LDG prefetch.
// COLS=8 on layer 2 is bit-identical to the MEASURED 33.2us kernel.
// COLS=16 on layer 3 keeps the proven 16-ull accumulator profile.
// ---------------------------------------------------------------------------
template <int DIN, int DOUT, int COLS, bool RELU>
__global__ void __launch_bounds__(256)
combine_pers_kernel(const float* __restrict__ xin,   // [n, DIN]
                    const float* __restrict__ S,     // [R, n, DIN]
                    const int* __restrict__ cnt,
                    const float* __restrict__ W,     // [R, DIN, DOUT]
                    const float* __restrict__ root,  // [DIN, DOUT]
                    const float* __restrict__ bias,  // [DOUT]
                    float* __restrict__ out, int n) {
    constexpr int SPLIT = DOUT / COLS;     // threads per node
    constexpr int NT    = 2;               // nodes per thread
    constexpr int NG    = 256 / SPLIT;     // node-groups per block
    constexpr int NPB   = NG * NT;         // nodes per tile
    constexpr int CH    = DIN / 4;
    constexpr int NC4   = 5 * CH;          // 4-row blocks (x + 4 relations)
    constexpr int WV    = COLS / 4;        // ulonglong2 per weight row slice

    __shared__ __align__(16) float sw[5 * DIN * DOUT];
    const int tid = threadIdx.x;
    {   // stage weights ONCE per block
        const float4* r4 = reinterpret_cast<const float4*>(root);
        const float4* w4 = reinterpret_cast<const float4*>(W);
        float4* s4 = reinterpret_cast<float4*>(sw);
        for (int i = tid; i < DIN * DOUT / 4; i += 256) s4[i] = __ldg(r4 + i);
        for (int i = tid; i < NREL * DIN * DOUT / 4; i += 256)
            s4[DIN * DOUT / 4 + i] = __ldg(w4 + i);
    }
    __syncthreads();

    const int ng = tid / SPLIT;
    const int sp = tid % SPLIT;
    const float* wbase = sw + sp * COLS;
    const float4* x4 = reinterpret_cast<const float4*>(xin);
    const ull* bb = reinterpret_cast<const ull*>(bias + sp * COLS);

    for (int tile = blockIdx.x * NPB; tile < n; tile += gridDim.x * NPB) {
        int nodev[NT];
        bool valid[NT];
        float sc[NT][5];
#pragma unroll
        for (int i = 0; i < NT; i++) {
            int nd = tile + ng + i * NG;
            valid[i] = nd < n;
            nodev[i] = valid[i] ? nd : 0;
            sc[i][0] = 1.0f;
#pragma unroll
            for (int r = 0; r < NREL; r++) {
                int c = __ldg(cnt + r * n + nodev[i]);
                sc[i][r + 1] = 1.0f / (float)(c > 1 ? c : 1);
            }
        }

        ull acc[NT][COLS / 2];
#pragma unroll
        for (int i = 0; i < NT; i++)
#pragma unroll
            for (int j = 0; j < COLS / 2; j++) acc[i][j] = bb[j];

        float4 vcur[NT], vnxt[NT];
#pragma unroll
        for (int i = 0; i < NT; i++)
            vcur[i] = __ldg(x4 + (size_t)nodev[i] * CH);

#pragma unroll
        for (int b = 0; b < NC4; b++) {
            const int rb = b / CH;
            const int c4 = b % CH;
            if (b + 1 < NC4) {
                const int rbn = (b + 1) / CH;
                const int c4n = (b + 1) % CH;
#pragma unroll
                for (int i = 0; i < NT; i++) {
                    const float* base = (rbn == 0)
                        ? xin + (size_t)nodev[i] * DIN
                        : S + ((size_t)(rbn - 1) * n + nodev[i]) * DIN;
                    vnxt[i] = __ldg(reinterpret_cast<const float4*>(base) + c4n);
                }
            }
            ulonglong2 w[4][WV];
#pragma unroll
            for (int k = 0; k < 4; k++) {
                const ulonglong2* wp = reinterpret_cast<const ulonglong2*>(
                    wbase + (rb * DIN + c4 * 4 + k) * DOUT);
#pragma unroll
                for (int j = 0; j < WV; j++) w[k][j] = wp[j];
            }
            float vs[NT][4];
#pragma unroll
            for (int i = 0; i < NT; i++) {
                const float s0 = sc[i][rb];
                vs[i][0] = vcur[i].x * s0;
                vs[i][1] = vcur[i].y * s0;
                vs[i][2] = vcur[i].z * s0;
                vs[i][3] = vcur[i].w * s0;
            }
#pragma unroll
            for (int k = 0; k < 4; k++) {
#pragma unroll
                for (int i = 0; i < NT; i++) {
                    const ull v2 = bcast2(vs[i][k]);
#pragma unroll
                    for (int j = 0; j < WV; j++) {
                        ffma2(acc[i][2 * j],     v2, w[k][j].x);
                        ffma2(acc[i][2 * j + 1], v2, w[k][j].y);
                    }
                }
            }
#pragma unroll
            for (int i = 0; i < NT; i++) vcur[i] = vnxt[i];
        }

#pragma unroll
        for (int i = 0; i < NT; i++) {
            if (!valid[i]) continue;
            float* op = out + (size_t)nodev[i] * DOUT + sp * COLS;
#pragma unroll
            for (int j = 0; j < COLS / 2; j++) {
                float2 f = *reinterpret_cast<float2*>(&acc[i][j]);
                if (RELU) {
                    f.x = fmaxf(f.x, 0.0f);
                    f.y = fmaxf(f.y, 0.0f);
                }
                reinterpret_cast<float2*>(op)[j] = f;
            }
        }
    }
}

// ---------------------------------------------------------------------------
// Launcher: memsets -> (scatter[+count], combine) x 3 layers
// ---------------------------------------------------------------------------
extern "C" void kernel_launch(void* const* d_in, const int* in_sizes, int n_in,
                              void* d_out, int out_size) {
    const float* x     = (const float*)d_in[0];
    const int*   ei    = (const int*)d_in[1];   // [2, E]: src then dst
    const int*   et    = (const int*)d_in[2];
    const float* W1    = (const float*)d_in[3];
    const float* root1 = (const float*)d_in[4];
    const float* b1    = (const float*)d_in[5];
    const float* W2    = (const float*)d_in[6];
    const float* root2 = (const float*)d_in[7];
    const float* b2    = (const float*)d_in[8];
    const float* W3    = (const float*)d_in[9];
    const float* root3 = (const float*)d_in[10];
    const float* b3    = (const float*)d_in[11];
    float* out = (float*)d_out;

    const int n = in_sizes[0] / 16;
    const int e = in_sizes[2];
    const int* src = ei;
    const int* dst = ei + e;

    float *pS1, *pS2, *pS3, *ph1, *ph2;
    int* pcnt;
    cudaGetSymbolAddress((void**)&pS1, g_S1);
    cudaGetSymbolAddress((void**)&pS2, g_S2);
    cudaGetSymbolAddress((void**)&pS3, g_S3);
    cudaGetSymbolAddress((void**)&pcnt, g_cnt);
    cudaGetSymbolAddress((void**)&ph1, g_h1);
    cudaGetSymbolAddress((void**)&ph2, g_h2);

    cudaMemsetAsync(pS1, 0, sizeof(float) * NREL * NNODES * 16);
    cudaMemsetAsync(pS2, 0, sizeof(float) * NREL * NNODES * 16);
    cudaMemsetAsync(pS3, 0, sizeof(float) * NREL * NNODES * 32);
    cudaMemsetAsync(pcnt, 0, sizeof(int) * NREL * NNODES);

    const int TB = 256;
    const int CB = 128;
    const int cgrid = (n + CB - 1) / CB;

    // Layer 1: 16 -> 16, relu (champion; scatter fuses the degree count)
    {
        int tot = e * 4;
        scatter_kernel<16, true><<<(tot + TB - 1) / TB, TB>>>(
            x, src, dst, et, pS1, pcnt, n, e);
        combine_kernel<16, 16, true><<<cgrid, CB>>>(
            x, pS1, pcnt, W1, root1, b1, ph1, n);
    }

    // Layer 2: 16 -> 32, relu (persistent COLS=8 — measured 33.2us)
    {
        int tot = e * 4;
        scatter_kernel<16, false><<<(tot + TB - 1) / TB, TB>>>(
            ph1, src, dst, et, pS2, pcnt, n, e);
        combine_pers_kernel<16, 32, 8, true><<<444, 256>>>(
            ph1, pS2, pcnt, W2, root2, b2, ph2, n);
    }

    // Layer 3: 32 -> 64, no relu — THE ONE CHANGE: persistent COLS=16
    // (SPLIT=4, NT=2; 16-ull no-spill acc profile; LDS:FFMA2 = 1:4)
    {
        int tot = e * 8;
        scatter_kernel<32, false><<<(tot + TB - 1) / TB, TB>>>(
            ph2, src, dst, et, pS3, pcnt, n, e);
        combine_pers_kernel<32, 64, 16, false><<<444, 256>>>(
            ph2, pS3, pcnt, W3, root3, b3, out, n);
    }
}

// round 16
// speedup vs baseline: 1.1975x; 1.1975x over previous
#include <cuda_runtime.h>

#define NNODES 100000
#define NEDGES 1600000
#define NREL 4

// Scratch (static __device__ arrays — allocation-free per harness rules)
__device__ __align__(16) float g_S1[NREL * NNODES * 16];  // 25.6 MB
__device__ __align__(16) float g_S2[NREL * NNODES * 16];  // 25.6 MB
__device__ __align__(16) float g_S3[NREL * NNODES * 32];  // 51.2 MB
__device__ int   g_cnt[NREL * NNODES];                    // 1.6 MB
__device__ __align__(16) float g_h1[NNODES * 16];
__device__ __align__(16) float g_h2[NNODES * 32];

typedef unsigned long long ull;

// ---------------------------------------------------------------------------
// f32x2 packed-FMA helpers (sm_100+)
// ---------------------------------------------------------------------------
__device__ __forceinline__ void ffma2(ull& acc, ull a, ull b) {
    asm("fma.rn.f32x2 %0, %1, %2, %0;" : "+l"(acc) : "l"(a), "l"(b));
}
__device__ __forceinline__ ull bcast2(float v) {
    ull r;
    unsigned int u = __float_as_uint(v);
    asm("mov.b64 %0, {%1, %1};" : "=l"(r) : "r"(u));
    return r;
}

// Multiply-accumulate one weight row (COLS floats, broadcast from smem) by a
// scalar input value into packed accumulators.
template <int COLS>
__device__ __forceinline__ void mac_row(ull* acc,
                                        const float* __restrict__ wrow,
                                        float v) {
    const ull v2 = bcast2(v);
#pragma unroll
    for (int j = 0; j < COLS / 4; j++) {
        ulonglong2 w = *reinterpret_cast<const ulonglong2*>(wrow + 4 * j);
        ffma2(acc[2 * j], v2, w.x);
        ffma2(acc[2 * j + 1], v2, w.y);
    }
}

// ---------------------------------------------------------------------------
// Scatter: S[r, dst, :] += h[src, :] via vectorized L2 reductions.
// (Champion, unchanged.)
// ---------------------------------------------------------------------------
template <int DIN, bool COUNT>
__global__ void scatter_kernel(const float* __restrict__ h,
                               const int* __restrict__ src,
                               const int* __restrict__ dst,
                               const int* __restrict__ et,
                               float* __restrict__ S,
                               int* __restrict__ cnt, int n, int e) {
    constexpr int CH = DIN / 4;
    int t = blockIdx.x * blockDim.x + threadIdx.x;
    int ed = t / CH;
    int c  = t - ed * CH;
    if (ed >= e) return;
    int s = __ldg(src + ed);
    int d = __ldg(dst + ed);
    int r = __ldg(et + ed);
    const float4 v = *reinterpret_cast<const float4*>(h + (size_t)s * DIN + c * 4);
    float* p = S + ((size_t)r * n + d) * DIN + c * 4;
    asm volatile("red.global.add.v4.f32 [%0], {%1,%2,%3,%4};"
                 :: "l"(p), "f"(v.x), "f"(v.y), "f"(v.z), "f"(v.w)
                 : "memory");
    if (COUNT && c == 0) atomicAdd(cnt + r * n + d, 1);
}

// ---------------------------------------------------------------------------
// Champion combine (fat thread; layers 1 & 3):
//   out[i] = bias + x[i]@root + sum_r (S[r,i]/max(cnt,1)) @ W_r
// ---------------------------------------------------------------------------
template <int DIN, int DOUT, bool RELU>
__global__ void __launch_bounds__(128)
combine_kernel(const float* __restrict__ xin,
               const float* __restrict__ S,
               const int* __restrict__ cnt,
               const float* __restrict__ W,     // [R, DIN, DOUT]
               const float* __restrict__ root,  // [DIN, DOUT]
               const float* __restrict__ bias,  // [DOUT]
               float* __restrict__ out, int n) {
    __shared__ __align__(16) float sw[5 * DIN * DOUT];
    const int tid = threadIdx.x;
    for (int i = tid; i < DIN * DOUT; i += 128) sw[i] = root[i];
    for (int i = tid; i < NREL * DIN * DOUT; i += 128) sw[DIN * DOUT + i] = W[i];
    __syncthreads();

    const int node = blockIdx.x * 128 + tid;
    if (node >= n) return;

    ull acc[DOUT / 2];
#pragma unroll
    for (int j = 0; j < DOUT / 2; j++)
        acc[j] = reinterpret_cast<const ull*>(bias)[j];

    float inv[NREL];
#pragma unroll
    for (int r = 0; r < NREL; r++) {
        int c = __ldg(cnt + r * n + node);
        inv[r] = 1.0f / (float)(c > 1 ? c : 1);
    }

#pragma unroll
    for (int rb = 0; rb < 5; rb++) {
        const float scale = (rb == 0) ? 1.0f : inv[rb - 1];
        const float4* __restrict__ base = reinterpret_cast<const float4*>(
            (rb == 0) ? xin + (size_t)node * DIN
                      : S + ((size_t)(rb - 1) * n + node) * DIN);
        const float* __restrict__ wr = sw + rb * DIN * DOUT;
        for (int c4 = 0; c4 < DIN / 4; c4++) {
            float4 v4 = __ldg(base + c4);
            mac_row<DOUT>(acc, wr + (c4 * 4 + 0) * DOUT, v4.x * scale);
            mac_row<DOUT>(acc, wr + (c4 * 4 + 1) * DOUT, v4.y * scale);
            mac_row<DOUT>(acc, wr + (c4 * 4 + 2) * DOUT, v4.z * scale);
            mac_row<DOUT>(acc, wr + (c4 * 4 + 3) * DOUT, v4.w * scale);
        }
    }

    float* op = out + (size_t)node * DOUT;
#pragma unroll
    for (int j = 0; j < DOUT / 2; j++) {
        float2 f = *reinterpret_cast<float2*>(&acc[j]);
        if (RELU) {
            f.x = fmaxf(f.x, 0.0f);
            f.y = fmaxf(f.y, 0.0f);
        }
        reinterpret_cast<float2*>(op)[j] = f;
    }
}

// ---------------------------------------------------------------------------
// Persistent combine (layer 2, COLS=8 — measured 33.2us config, unchanged)
// ---------------------------------------------------------------------------
template <int DIN, int DOUT, int COLS, bool RELU>
__global__ void __launch_bounds__(256)
combine_pers_kernel(const float* __restrict__ xin,   // [n, DIN]
                    const float* __restrict__ S,     // [R, n, DIN]
                    const int* __restrict__ cnt,
                    const float* __restrict__ W,     // [R, DIN, DOUT]
                    const float* __restrict__ root,  // [DIN, DOUT]
                    const float* __restrict__ bias,  // [DOUT]
                    float* __restrict__ out, int n) {
    constexpr int SPLIT = DOUT / COLS;
    constexpr int NT    = 2;
    constexpr int NG    = 256 / SPLIT;
    constexpr int NPB   = NG * NT;
    constexpr int CH    = DIN / 4;
    constexpr int NC4   = 5 * CH;
    constexpr int WV    = COLS / 4;

    __shared__ __align__(16) float sw[5 * DIN * DOUT];
    const int tid = threadIdx.x;
    {
        const float4* r4 = reinterpret_cast<const float4*>(root);
        const float4* w4 = reinterpret_cast<const float4*>(W);
        float4* s4 = reinterpret_cast<float4*>(sw);
        for (int i = tid; i < DIN * DOUT / 4; i += 256) s4[i] = __ldg(r4 + i);
        for (int i = tid; i < NREL * DIN * DOUT / 4; i += 256)
            s4[DIN * DOUT / 4 + i] = __ldg(w4 + i);
    }
    __syncthreads();

    const int ng = tid / SPLIT;
    const int sp = tid % SPLIT;
    const float* wbase = sw + sp * COLS;
    const float4* x4 = reinterpret_cast<const float4*>(xin);
    const ull* bb = reinterpret_cast<const ull*>(bias + sp * COLS);

    for (int tile = blockIdx.x * NPB; tile < n; tile += gridDim.x * NPB) {
        int nodev[NT];
        bool valid[NT];
        float sc[NT][5];
#pragma unroll
        for (int i = 0; i < NT; i++) {
            int nd = tile + ng + i * NG;
            valid[i] = nd < n;
            nodev[i] = valid[i] ? nd : 0;
            sc[i][0] = 1.0f;
#pragma unroll
            for (int r = 0; r < NREL; r++) {
                int c = __ldg(cnt + r * n + nodev[i]);
                sc[i][r + 1] = 1.0f / (float)(c > 1 ? c : 1);
            }
        }

        ull acc[NT][COLS / 2];
#pragma unroll
        for (int i = 0; i < NT; i++)
#pragma unroll
            for (int j = 0; j < COLS / 2; j++) acc[i][j] = bb[j];

        float4 vcur[NT], vnxt[NT];
#pragma unroll
        for (int i = 0; i < NT; i++)
            vcur[i] = __ldg(x4 + (size_t)nodev[i] * CH);

#pragma unroll
        for (int b = 0; b < NC4; b++) {
            const int rb = b / CH;
            const int c4 = b % CH;
            if (b + 1 < NC4) {
                const int rbn = (b + 1) / CH;
                const int c4n = (b + 1) % CH;
#pragma unroll
                for (int i = 0; i < NT; i++) {
                    const float* base = (rbn == 0)
                        ? xin + (size_t)nodev[i] * DIN
                        : S + ((size_t)(rbn - 1) * n + nodev[i]) * DIN;
                    vnxt[i] = __ldg(reinterpret_cast<const float4*>(base) + c4n);
                }
            }
            ulonglong2 w[4][WV];
#pragma unroll
            for (int k = 0; k < 4; k++) {
                const ulonglong2* wp = reinterpret_cast<const ulonglong2*>(
                    wbase + (rb * DIN + c4 * 4 + k) * DOUT);
#pragma unroll
                for (int j = 0; j < WV; j++) w[k][j] = wp[j];
            }
            float vs[NT][4];
#pragma unroll
            for (int i = 0; i < NT; i++) {
                const float s0 = sc[i][rb];
                vs[i][0] = vcur[i].x * s0;
                vs[i][1] = vcur[i].y * s0;
                vs[i][2] = vcur[i].z * s0;
                vs[i][3] = vcur[i].w * s0;
            }
#pragma unroll
            for (int k = 0; k < 4; k++) {
#pragma unroll
                for (int i = 0; i < NT; i++) {
                    const ull v2 = bcast2(vs[i][k]);
#pragma unroll
                    for (int j = 0; j < WV; j++) {
                        ffma2(acc[i][2 * j],     v2, w[k][j].x);
                        ffma2(acc[i][2 * j + 1], v2, w[k][j].y);
                    }
                }
            }
#pragma unroll
            for (int i = 0; i < NT; i++) vcur[i] = vnxt[i];
        }

#pragma unroll
        for (int i = 0; i < NT; i++) {
            if (!valid[i]) continue;
            float* op = out + (size_t)nodev[i] * DOUT + sp * COLS;
#pragma unroll
            for (int j = 0; j < COLS / 2; j++) {
                float2 f = *reinterpret_cast<float2*>(&acc[i][j]);
                if (RELU) {
                    f.x = fmaxf(f.x, 0.0f);
                    f.y = fmaxf(f.y, 0.0f);
                }
                reinterpret_cast<float2*>(op)[j] = f;
            }
        }
    }
}

// ---------------------------------------------------------------------------
// Launcher. ONE CHANGE vs the 289.2us champion: memsets are placed
// immediately before the phase that uses them (L2-residency: each S buffer's
// lines go memset -> atomic-RMW -> combine-read without leaving L2, instead
// of 104MB of upfront dirty lines thrashing the 126MB L2 every phase).
// ---------------------------------------------------------------------------
extern "C" void kernel_launch(void* const* d_in, const int* in_sizes, int n_in,
                              void* d_out, int out_size) {
    const float* x     = (const float*)d_in[0];
    const int*   ei    = (const int*)d_in[1];   // [2, E]: src then dst
    const int*   et    = (const int*)d_in[2];
    const float* W1    = (const float*)d_in[3];
    const float* root1 = (const float*)d_in[4];
    const float* b1    = (const float*)d_in[5];
    const float* W2    = (const float*)d_in[6];
    const float* root2 = (const float*)d_in[7];
    const float* b2    = (const float*)d_in[8];
    const float* W3    = (const float*)d_in[9];
    const float* root3 = (const float*)d_in[10];
    const float* b3    = (const float*)d_in[11];
    float* out = (float*)d_out;

    const int n = in_sizes[0] / 16;
    const int e = in_sizes[2];
    const int* src = ei;
    const int* dst = ei + e;

    float *pS1, *pS2, *pS3, *ph1, *ph2;
    int* pcnt;
    cudaGetSymbolAddress((void**)&pS1, g_S1);
    cudaGetSymbolAddress((void**)&pS2, g_S2);
    cudaGetSymbolAddress((void**)&pS3, g_S3);
    cudaGetSymbolAddress((void**)&pcnt, g_cnt);
    cudaGetSymbolAddress((void**)&ph1, g_h1);
    cudaGetSymbolAddress((void**)&ph2, g_h2);

    const int TB = 256;
    const int CB = 128;
    const int cgrid = (n + CB - 1) / CB;

    // Layer 1: 16 -> 16, relu (zero S1+cnt right before use)
    cudaMemsetAsync(pS1, 0, sizeof(float) * NREL * NNODES * 16);
    cudaMemsetAsync(pcnt, 0, sizeof(int) * NREL * NNODES);
    {
        int tot = e * 4;
        scatter_kernel<16, true><<<(tot + TB - 1) / TB, TB>>>(
            x, src, dst, et, pS1, pcnt, n, e);
        combine_kernel<16, 16, true><<<cgrid, CB>>>(
            x, pS1, pcnt, W1, root1, b1, ph1, n);
    }

    // Layer 2: 16 -> 32, relu (zero S2 right before use; persistent combine)
    cudaMemsetAsync(pS2, 0, sizeof(float) * NREL * NNODES * 16);
    {
        int tot = e * 4;
        scatter_kernel<16, false><<<(tot + TB - 1) / TB, TB>>>(
            ph1, src, dst, et, pS2, pcnt, n, e);
        combine_pers_kernel<16, 32, 8, true><<<444, 256>>>(
            ph1, pS2, pcnt, W2, root2, b2, ph2, n);
    }

    // Layer 3: 32 -> 64, no relu (zero S3 right before use; champion combine)
    cudaMemsetAsync(pS3, 0, sizeof(float) * NREL * NNODES * 32);
    {
        int tot = e * 8;
        scatter_kernel<32, false><<<(tot + TB - 1) / TB, TB>>>(
            ph2, src, dst, et, pS3, pcnt, n, e);
        combine_kernel<32, 64, false><<<cgrid, CB>>>(
            ph2, pS3, pcnt, W3, root3, b3, out, n);
    }
}